// round 17
// baseline (speedup 1.0000x reference)
#include <cuda_runtime.h>

#define NN   50000
#define NE   800000
#define FIN  128
#define EDIM 16
#define HIDD 64
#define HC1  128
#define NG   50
#define NCLS 2

typedef unsigned long long u64t;

// ---------------- f32x2 packed helpers (sm_103a FFMA2 path) ----------------
__device__ __forceinline__ u64t pack2(float lo, float hi) {
    u64t r;
    asm("mov.b64 %0, {%1, %2};" : "=l"(r)
        : "r"(__float_as_uint(lo)), "r"(__float_as_uint(hi)));
    return r;
}
__device__ __forceinline__ void unpack2(u64t v, float& lo, float& hi) {
    unsigned int a, b;
    asm("mov.b64 {%0, %1}, %2;" : "=r"(a), "=r"(b) : "l"(v));
    lo = __uint_as_float(a);
    hi = __uint_as_float(b);
}
__device__ __forceinline__ u64t fma2(u64t a, u64t b, u64t c) {
    u64t d;
    asm("fma.rn.f32x2 %0, %1, %2, %3;" : "=l"(d) : "l"(a), "l"(b), "l"(c));
    return d;
}

// ---------------- scratch (device globals; allocation-free) ----------------
__device__ float g_xp  [NN * HC1];
__device__ float g_xl1 [NN * HC1];
__device__ float g_xr1 [NN * HC1];
__device__ float g_agg1[NN * HC1];
__device__ float g_h   [NN * HC1];

__device__ float g_xp2 [NN * HIDD];
__device__ float g_xl2 [NN * HIDD];
__device__ float g_xr2 [NN * HIDD];
__device__ float g_agg2[NN * HIDD];
__device__ float g_h2  [NN * HIDD];

// CSR by destination.  Zero-initialized at module load; k_scan re-zeroes
// g_cnt (and stats accumulators) after consuming them, so every execution
// (correctness run + each graph replay) sees the same initial state.
__device__ int  g_cnt[NN];
__device__ int  g_off[NN + 1];
__device__ int  g_cur[NN];
__device__ int2 g_es [NE];   // (orig edge id, src node) in CSR order

__device__ float g_stats1[4 * HC1];
__device__ float g_stats2[4 * HIDD];
__device__ float g_gsum[NG * HIDD];
__device__ float g_gmax[NG * HIDD];
__device__ float g_gcnt[NG];

// ---------------- helpers ----------------
__device__ __forceinline__ int lower_bound_dev(const int* arr, int n, int key) {
    int lo = 0, hi = n;
    while (lo < hi) {
        int mid = (lo + hi) >> 1;
        if (arr[mid] < key) lo = mid + 1; else hi = mid;
    }
    return lo;
}

// ---------------- CSR build ----------------
__global__ void k_hist(const int* __restrict__ dst) {
    int stride = gridDim.x * blockDim.x;
    for (int e = blockIdx.x * blockDim.x + threadIdx.x; e < NE; e += stride)
        atomicAdd(&g_cnt[dst[e]], 1);
}

// prefix-scan of counts -> off/cur; then zero cnt + BN stat accumulators.
__global__ void k_scan() {
    __shared__ int sh[1024];
    int t = threadIdx.x;
    const int CH = (NN + 1023) >> 10;
    int base = t * CH;
    int s = 0;
    for (int i = 0; i < CH; i++) { int idx = base + i; if (idx < NN) s += g_cnt[idx]; }
    sh[t] = s;
    __syncthreads();
    for (int off = 1; off < 1024; off <<= 1) {
        int v = (t >= off) ? sh[t - off] : 0;
        __syncthreads();
        sh[t] += v;
        __syncthreads();
    }
    int run = (t == 0) ? 0 : sh[t - 1];
    for (int i = 0; i < CH; i++) {
        int idx = base + i;
        if (idx < NN) {
            g_off[idx] = run;
            g_cur[idx] = run;
            run += g_cnt[idx];
            g_cnt[idx] = 0;          // reset for next execution
        }
    }
    if (t == 1023) g_off[NN] = sh[1023];
    if (t < 2 * HC1)  g_stats1[t] = 0.f;
    if (t < 2 * HIDD) g_stats2[t] = 0.f;
}

// ---------------- GEMM body (f32x2 packed inner loop) ----------------
template<int K, int M>
__device__ __forceinline__ void gemm3_body(
        int bx, int by,
        const float* __restrict__ A,
        const float* __restrict__ W0, const float* __restrict__ b0, float* __restrict__ C0,
        const float* __restrict__ W1, const float* __restrict__ b1, float* __restrict__ C1,
        const float* __restrict__ W2, const float* __restrict__ b2, float* __restrict__ C2,
        int n) {
    const float* W    = (by == 0) ? W0 : (by == 1) ? W1 : W2;
    const float* bias = (by == 0) ? b0 : (by == 1) ? b1 : b2;
    float* C          = (by == 0) ? C0 : (by == 1) ? C1 : C2;

    constexpr int CT = M / 8;
    constexpr int RT = 256 / CT;
    constexpr int BM = RT * 8;
    constexpr int BK = 32;

    __shared__ float sA[BK][BM + 4];
    __shared__ float sB[BK][M];

    int tx = threadIdx.x % CT, ty = threadIdx.x / CT;
    int row0 = bx * BM;

    u64t accp[8][4];
#pragma unroll
    for (int i = 0; i < 8; i++)
#pragma unroll
        for (int j = 0; j < 4; j++) accp[i][j] = 0ull;

    for (int k0 = 0; k0 < K; k0 += BK) {
        for (int v = threadIdx.x; v < BM * BK / 4; v += 256) {
            int idx = v * 4;
            int r = idx / BK, kk = idx % BK;
            float4 a = make_float4(0.f, 0.f, 0.f, 0.f);
            if (row0 + r < n) a = *(const float4*)&A[(size_t)(row0 + r) * K + k0 + kk];
            sA[kk + 0][r] = a.x;
            sA[kk + 1][r] = a.y;
            sA[kk + 2][r] = a.z;
            sA[kk + 3][r] = a.w;
        }
        for (int v = threadIdx.x; v < BK * M / 4; v += 256) {
            int idx = v * 4;
            int kk = idx / M, c = idx % M;
            *(float4*)&sB[kk][c] = *(const float4*)&W[(size_t)(k0 + kk) * M + c];
        }
        __syncthreads();
#pragma unroll
        for (int kk = 0; kk < BK; kk++) {
            float4 a0 = *(const float4*)&sA[kk][ty * 8];
            float4 a1 = *(const float4*)&sA[kk][ty * 8 + 4];
            float ra[8] = {a0.x, a0.y, a0.z, a0.w, a1.x, a1.y, a1.z, a1.w};
            const ulonglong2* pb = (const ulonglong2*)&sB[kk][tx * 8];
            ulonglong2 b01 = pb[0];
            ulonglong2 b23 = pb[1];
            u64t rb[4] = {b01.x, b01.y, b23.x, b23.y};
#pragma unroll
            for (int i = 0; i < 8; i++) {
                u64t rap = pack2(ra[i], ra[i]);
#pragma unroll
                for (int j = 0; j < 4; j++) accp[i][j] = fma2(rap, rb[j], accp[i][j]);
            }
        }
        __syncthreads();
    }

    float bb[8];
#pragma unroll
    for (int j = 0; j < 8; j++) bb[j] = bias[tx * 8 + j];
#pragma unroll
    for (int i = 0; i < 8; i++) {
        int r = row0 + ty * 8 + i;
        if (r < n) {
            float o[8];
#pragma unroll
            for (int j = 0; j < 4; j++) unpack2(accp[i][j], o[2 * j], o[2 * j + 1]);
            float4 o0 = make_float4(o[0] + bb[0], o[1] + bb[1], o[2] + bb[2], o[3] + bb[3]);
            float4 o1 = make_float4(o[4] + bb[4], o[5] + bb[5], o[6] + bb[6], o[7] + bb[7]);
            *(float4*)&C[(size_t)r * M + tx * 8]     = o0;
            *(float4*)&C[(size_t)r * M + tx * 8 + 4] = o1;
        }
    }
}

// Layer-1: fused CSR-scatter + triple GEMM (independent work, one launch).
#define SCAT_BLOCKS 1024
#define GEMM1_BX ((NN + 127) / 128)   // 391

__global__ void __launch_bounds__(256)
k_scatter_gemm1(const int* __restrict__ src, const int* __restrict__ dst,
                const float* __restrict__ A,
                const float* __restrict__ W0, const float* __restrict__ b0, float* __restrict__ C0,
                const float* __restrict__ W1, const float* __restrict__ b1, float* __restrict__ C1,
                const float* __restrict__ W2, const float* __restrict__ b2, float* __restrict__ C2) {
    if (blockIdx.x < SCAT_BLOCKS) {
        int stride = SCAT_BLOCKS * 256;
        for (int e = blockIdx.x * 256 + threadIdx.x; e < NE; e += stride) {
            int p = atomicAdd(&g_cur[dst[e]], 1);
            g_es[p] = make_int2(e, src[e]);
        }
    } else {
        int gb = blockIdx.x - SCAT_BLOCKS;
        gemm3_body<FIN, HC1>(gb % GEMM1_BX, gb / GEMM1_BX,
                             A, W0, b0, C0, W1, b1, C1, W2, b2, C2, NN);
    }
}

// Layer-2 GEMM (standalone)
__global__ void __launch_bounds__(256)
k_gemm3_l2(const float* __restrict__ A,
           const float* __restrict__ W0, const float* __restrict__ b0, float* __restrict__ C0,
           const float* __restrict__ W1, const float* __restrict__ b1, float* __restrict__ C1,
           const float* __restrict__ W2, const float* __restrict__ b2, float* __restrict__ C2) {
    gemm3_body<HC1, HIDD>(blockIdx.x, blockIdx.y,
                          A, W0, b0, C0, W1, b1, C1, W2, b2, C2, NN);
}

// ---------------- layer-1 GATv2: warp/node, We in smem, 4-edge weight amortization ----
// Each smem weight row is loaded ONCE per 4-edge batch (weight-LDS wavefronts
// per edge halved vs the 2-edge version). Epilogue per edge unchanged.
__global__ void __launch_bounds__(128)
k_gat1(const float* __restrict__ eattr, const float* __restrict__ We,
       const float* __restrict__ att) {
    __shared__ float sWe[EDIM * HC1];
    for (int i = threadIdx.x; i < EDIM * HC1; i += 128)
        sWe[i] = We[i];
    __syncthreads();

    int lane = threadIdx.x & 31;
    int w = (blockIdx.x * blockDim.x + threadIdx.x) >> 5;
    int nw = (gridDim.x * blockDim.x) >> 5;
    int c0 = lane * 4;
    const float4 rA = *(const float4*)(att + c0);

    for (int node = w; node < NN; node += nw) {
        int beg = g_off[node], end = g_off[node + 1];
        const float4 xr = *(const float4*)&g_xr1[(size_t)node * HC1 + c0];

        float den = 0.f;
        float4 acc = make_float4(0.f, 0.f, 0.f, 0.f);

        int i = beg;
        for (; i + 4 <= end; i += 4) {
            float4 ea[4], xl[4];
#pragma unroll
            for (int e = 0; e < 4; e++) {
                int2 es = g_es[i + e];
                ea[e] = make_float4(0.f, 0.f, 0.f, 0.f);
                if (lane < 4) ea[e] = *(const float4*)&eattr[(size_t)es.x * EDIM + lane * 4];
                xl[e] = *(const float4*)&g_xl1[(size_t)es.y * HC1 + c0];
            }

            u64t ev0[4] = {0ull, 0ull, 0ull, 0ull};
            u64t ev1[4] = {0ull, 0ull, 0ull, 0ull};
#pragma unroll
            for (int q = 0; q < 4; q++) {
                float sv[4][4];
#pragma unroll
                for (int e = 0; e < 4; e++) {
                    sv[e][0] = __shfl_sync(0xffffffffu, ea[e].x, q);
                    sv[e][1] = __shfl_sync(0xffffffffu, ea[e].y, q);
                    sv[e][2] = __shfl_sync(0xffffffffu, ea[e].z, q);
                    sv[e][3] = __shfl_sync(0xffffffffu, ea[e].w, q);
                }
#pragma unroll
                for (int j = 0; j < 4; j++) {
                    ulonglong2 wv = *(const ulonglong2*)&sWe[(4 * q + j) * HC1 + c0];
#pragma unroll
                    for (int e = 0; e < 4; e++) {
                        u64t pe = pack2(sv[e][j], sv[e][j]);
                        ev0[e] = fma2(pe, wv.x, ev0[e]);
                        ev1[e] = fma2(pe, wv.y, ev1[e]);
                    }
                }
            }
#pragma unroll
            for (int e = 0; e < 4; e++) {
                float v0, v1, v2, v3;
                unpack2(ev0[e], v0, v1);
                unpack2(ev1[e], v2, v3);
                float m0 = xl[e].x + xr.x + v0, m1 = xl[e].y + xr.y + v1;
                float m2 = xl[e].z + xr.z + v2, m3 = xl[e].w + xr.w + v3;
                m0 = (m0 > 0.f) ? m0 : 0.2f * m0;
                m1 = (m1 > 0.f) ? m1 : 0.2f * m1;
                m2 = (m2 > 0.f) ? m2 : 0.2f * m2;
                m3 = (m3 > 0.f) ? m3 : 0.2f * m3;
                float p = m0 * rA.x + m1 * rA.y + m2 * rA.z + m3 * rA.w;
#pragma unroll
                for (int o = 8; o; o >>= 1) p += __shfl_xor_sync(0xffffffffu, p, o);
                p = fminf(fmaxf(p, -60.f), 60.f);
                float a = __expf(p);
                den += a;
                acc.x = fmaf(a, xl[e].x, acc.x);
                acc.y = fmaf(a, xl[e].y, acc.y);
                acc.z = fmaf(a, xl[e].z, acc.z);
                acc.w = fmaf(a, xl[e].w, acc.w);
            }
        }
        for (; i < end; i++) {
            int2 es = g_es[i];
            float4 ea0 = make_float4(0.f, 0.f, 0.f, 0.f);
            if (lane < 4) ea0 = *(const float4*)&eattr[(size_t)es.x * EDIM + lane * 4];
            const float4 xl0 = *(const float4*)&g_xl1[(size_t)es.y * HC1 + c0];
            u64t ev0 = 0ull, ev1 = 0ull;
#pragma unroll
            for (int q = 0; q < 4; q++) {
                float s0 = __shfl_sync(0xffffffffu, ea0.x, q);
                float s1 = __shfl_sync(0xffffffffu, ea0.y, q);
                float s2 = __shfl_sync(0xffffffffu, ea0.z, q);
                float s3 = __shfl_sync(0xffffffffu, ea0.w, q);
#pragma unroll
                for (int j = 0; j < 4; j++) {
                    ulonglong2 wv = *(const ulonglong2*)&sWe[(4 * q + j) * HC1 + c0];
                    float av = (j == 0) ? s0 : (j == 1) ? s1 : (j == 2) ? s2 : s3;
                    u64t pa = pack2(av, av);
                    ev0 = fma2(pa, wv.x, ev0);
                    ev1 = fma2(pa, wv.y, ev1);
                }
            }
            float v0, v1, v2, v3;
            unpack2(ev0, v0, v1);
            unpack2(ev1, v2, v3);
            float m0 = xl0.x + xr.x + v0, m1 = xl0.y + xr.y + v1;
            float m2 = xl0.z + xr.z + v2, m3 = xl0.w + xr.w + v3;
            m0 = (m0 > 0.f) ? m0 : 0.2f * m0;
            m1 = (m1 > 0.f) ? m1 : 0.2f * m1;
            m2 = (m2 > 0.f) ? m2 : 0.2f * m2;
            m3 = (m3 > 0.f) ? m3 : 0.2f * m3;
            float p = m0 * rA.x + m1 * rA.y + m2 * rA.z + m3 * rA.w;
#pragma unroll
            for (int o = 8; o; o >>= 1) p += __shfl_xor_sync(0xffffffffu, p, o);
            p = fminf(fmaxf(p, -60.f), 60.f);
            float a = __expf(p);
            den += a;
            acc.x = fmaf(a, xl0.x, acc.x);
            acc.y = fmaf(a, xl0.y, acc.y);
            acc.z = fmaf(a, xl0.z, acc.z);
            acc.w = fmaf(a, xl0.w, acc.w);
        }

        float inv = 1.f / (den + 1e-16f);
        *(float4*)&g_agg1[(size_t)node * HC1 + c0] =
            make_float4(acc.x * inv, acc.y * inv, acc.z * inv, acc.w * inv);
    }
}

// ---------------- layer-2 GATv2: warp/node, We in smem, 4-edge weight amortization ----
__global__ void __launch_bounds__(128)
k_gat2(const float* __restrict__ eattr, const float* __restrict__ We,
       const float* __restrict__ att) {
    __shared__ float sWe[EDIM * HIDD];
    for (int i = threadIdx.x; i < EDIM * HIDD; i += 128)
        sWe[i] = We[i];
    __syncthreads();

    int lane = threadIdx.x & 31;
    int w = (blockIdx.x * blockDim.x + threadIdx.x) >> 5;
    int nw = (gridDim.x * blockDim.x) >> 5;
    int c0 = lane * 2;
    const float2 rA = *(const float2*)(att + c0);

    for (int node = w; node < NN; node += nw) {
        int beg = g_off[node], end = g_off[node + 1];
        const float2 xr = *(const float2*)&g_xr2[(size_t)node * HIDD + c0];

        float den = 0.f;
        float2 acc = make_float2(0.f, 0.f);

        int i = beg;
        for (; i + 4 <= end; i += 4) {
            float4 ea[4];
            float2 xl[4];
#pragma unroll
            for (int e = 0; e < 4; e++) {
                int2 es = g_es[i + e];
                ea[e] = make_float4(0.f, 0.f, 0.f, 0.f);
                if (lane < 4) ea[e] = *(const float4*)&eattr[(size_t)es.x * EDIM + lane * 4];
                xl[e] = *(const float2*)&g_xl2[(size_t)es.y * HIDD + c0];
            }

            u64t ev[4] = {0ull, 0ull, 0ull, 0ull};
#pragma unroll
            for (int q = 0; q < 4; q++) {
                float sv[4][4];
#pragma unroll
                for (int e = 0; e < 4; e++) {
                    sv[e][0] = __shfl_sync(0xffffffffu, ea[e].x, q);
                    sv[e][1] = __shfl_sync(0xffffffffu, ea[e].y, q);
                    sv[e][2] = __shfl_sync(0xffffffffu, ea[e].z, q);
                    sv[e][3] = __shfl_sync(0xffffffffu, ea[e].w, q);
                }
#pragma unroll
                for (int j = 0; j < 4; j++) {
                    u64t wv = *(const u64t*)&sWe[(4 * q + j) * HIDD + c0];
#pragma unroll
                    for (int e = 0; e < 4; e++)
                        ev[e] = fma2(pack2(sv[e][j], sv[e][j]), wv, ev[e]);
                }
            }
#pragma unroll
            for (int e = 0; e < 4; e++) {
                float v0, v1;
                unpack2(ev[e], v0, v1);
                float m0 = xl[e].x + xr.x + v0, m1 = xl[e].y + xr.y + v1;
                m0 = (m0 > 0.f) ? m0 : 0.2f * m0;
                m1 = (m1 > 0.f) ? m1 : 0.2f * m1;
                float p = m0 * rA.x + m1 * rA.y;
#pragma unroll
                for (int o = 16; o; o >>= 1) p += __shfl_xor_sync(0xffffffffu, p, o);
                p = fminf(fmaxf(p, -60.f), 60.f);
                float a = __expf(p);
                den += a;
                acc.x = fmaf(a, xl[e].x, acc.x);
                acc.y = fmaf(a, xl[e].y, acc.y);
            }
        }
        for (; i < end; i++) {
            int2 es = g_es[i];
            float4 ea0 = make_float4(0.f, 0.f, 0.f, 0.f);
            if (lane < 4) ea0 = *(const float4*)&eattr[(size_t)es.x * EDIM + lane * 4];
            const float2 xl0 = *(const float2*)&g_xl2[(size_t)es.y * HIDD + c0];
            u64t ev0 = 0ull;
#pragma unroll
            for (int q = 0; q < 4; q++) {
                float s0 = __shfl_sync(0xffffffffu, ea0.x, q);
                float s1 = __shfl_sync(0xffffffffu, ea0.y, q);
                float s2 = __shfl_sync(0xffffffffu, ea0.z, q);
                float s3 = __shfl_sync(0xffffffffu, ea0.w, q);
#pragma unroll
                for (int j = 0; j < 4; j++) {
                    u64t wv = *(const u64t*)&sWe[(4 * q + j) * HIDD + c0];
                    float av = (j == 0) ? s0 : (j == 1) ? s1 : (j == 2) ? s2 : s3;
                    ev0 = fma2(pack2(av, av), wv, ev0);
                }
            }
            float v0, v1;
            unpack2(ev0, v0, v1);
            float m0 = xl0.x + xr.x + v0, m1 = xl0.y + xr.y + v1;
            m0 = (m0 > 0.f) ? m0 : 0.2f * m0;
            m1 = (m1 > 0.f) ? m1 : 0.2f * m1;
            float p = m0 * rA.x + m1 * rA.y;
#pragma unroll
            for (int o = 16; o; o >>= 1) p += __shfl_xor_sync(0xffffffffu, p, o);
            p = fminf(fmaxf(p, -60.f), 60.f);
            float a = __expf(p);
            den += a;
            acc.x = fmaf(a, xl0.x, acc.x);
            acc.y = fmaf(a, xl0.y, acc.y);
        }

        float inv = 1.f / (den + 1e-16f);
        *(float2*)&g_agg2[(size_t)node * HIDD + c0] =
            make_float2(acc.x * inv, acc.y * inv);
    }
}

// ---------------- batch norm (training mode, biased var) + ELU + skip ----------------
template<int M>
__global__ void k_bn_stats(const float* __restrict__ X, float* __restrict__ stats) {
    int c = threadIdx.x;
    float s = 0.f, q = 0.f;
    for (int r = blockIdx.x; r < NN; r += gridDim.x) {
        float v = X[(size_t)r * M + c];
        s += v; q += v * v;
    }
    atomicAdd(&stats[c], s);
    atomicAdd(&stats[M + c], q);
}

template<int M>
__global__ void k_bn_final(float* __restrict__ stats) {
    int c = threadIdx.x;
    float mu = stats[c] / (float)NN;
    float var = stats[M + c] / (float)NN - mu * mu;
    stats[2 * M + c] = mu;
    stats[3 * M + c] = rsqrtf(var + 1e-5f);
}

template<int M>
__global__ void k_bn_elu(const float* __restrict__ X, const float* __restrict__ stats,
                         const float* __restrict__ gam, const float* __restrict__ bet,
                         const float* __restrict__ skip, float* __restrict__ out) {
    int stride = gridDim.x * blockDim.x;
    int total = NN * M / 4;
    const float4* X4 = (const float4*)X;
    const float4* S4 = (const float4*)skip;
    float4* O4 = (float4*)out;
    for (int i = blockIdx.x * blockDim.x + threadIdx.x; i < total; i += stride) {
        int c = (i * 4) % M;
        float4 xv = X4[i], sv = S4[i];
        float4 o;
        float v;
        v = (xv.x - stats[2 * M + c])     * stats[3 * M + c]     * gam[c]     + bet[c]     + sv.x;
        o.x = (v > 0.f) ? v : expm1f(v);
        v = (xv.y - stats[2 * M + c + 1]) * stats[3 * M + c + 1] * gam[c + 1] + bet[c + 1] + sv.y;
        o.y = (v > 0.f) ? v : expm1f(v);
        v = (xv.z - stats[2 * M + c + 2]) * stats[3 * M + c + 2] * gam[c + 2] + bet[c + 2] + sv.z;
        o.z = (v > 0.f) ? v : expm1f(v);
        v = (xv.w - stats[2 * M + c + 3]) * stats[3 * M + c + 3] * gam[c + 3] + bet[c + 3] + sv.w;
        o.w = (v > 0.f) ? v : expm1f(v);
        O4[i] = o;
    }
}

// ---------------- pooling (batch is sorted) + classifier ----------------
__global__ void k_pool(const int* __restrict__ batch) {
    int g = blockIdx.x;
    int start = lower_bound_dev(batch, NN, g);
    int end   = lower_bound_dev(batch, NN, g + 1);
    int c = threadIdx.x & 63, sub = threadIdx.x >> 6;
    float s = 0.f, mx = -1e30f;
    for (int r = start + sub; r < end; r += 4) {
        float v = g_h2[(size_t)r * HIDD + c];
        s += v; mx = fmaxf(mx, v);
    }
    __shared__ float sh[256], shm[256];
    sh[threadIdx.x] = s; shm[threadIdx.x] = mx;
    __syncthreads();
    if (sub == 0) {
#pragma unroll
        for (int k = 1; k < 4; k++) {
            s += sh[c + k * 64];
            mx = fmaxf(mx, shm[c + k * 64]);
        }
        g_gsum[g * HIDD + c] = s;
        g_gmax[g * HIDD + c] = mx;
        if (c == 0) g_gcnt[g] = (float)(end - start);
    }
}

__global__ void k_classify(const float* __restrict__ W, const float* __restrict__ b,
                           float* __restrict__ out) {
    int i = threadIdx.x;
    if (i >= NG * NCLS) return;
    int g = i / NCLS, k = i % NCLS;
    float cnt = fmaxf(g_gcnt[g], 1.f);
    float acc = b[k];
#pragma unroll 4
    for (int j = 0; j < HIDD; j++) {
        acc = fmaf(g_gsum[g * HIDD + j] / cnt, W[j * NCLS + k], acc);
        acc = fmaf(g_gmax[g * HIDD + j], W[(HIDD + j) * NCLS + k], acc);
    }
    out[i] = acc;
}

// ---------------- launch ----------------
extern "C" void kernel_launch(void* const* d_in, const int* in_sizes, int n_in,
                              void* d_out, int out_size) {
    const float* x       = (const float*)d_in[0];
    const int*   eidx    = (const int*)  d_in[1];
    const float* eattr   = (const float*)d_in[2];
    const int*   batch   = (const int*)  d_in[3];
    const float* skip1_w = (const float*)d_in[4];
    const float* skip1_b = (const float*)d_in[5];
    const float* c1_wl   = (const float*)d_in[6];
    const float* c1_bl   = (const float*)d_in[7];
    const float* c1_wr   = (const float*)d_in[8];
    const float* c1_br   = (const float*)d_in[9];
    const float* c1_we   = (const float*)d_in[10];
    const float* c1_att  = (const float*)d_in[11];
    /* d_in[12] c1_bias: cancels inside training-mode BN */
    const float* bn1_g   = (const float*)d_in[13];
    const float* bn1_b   = (const float*)d_in[14];
    const float* skip2_w = (const float*)d_in[15];
    const float* skip2_b = (const float*)d_in[16];
    const float* c2_wl   = (const float*)d_in[17];
    const float* c2_bl   = (const float*)d_in[18];
    const float* c2_wr   = (const float*)d_in[19];
    const float* c2_br   = (const float*)d_in[20];
    const float* c2_we   = (const float*)d_in[21];
    const float* c2_att  = (const float*)d_in[22];
    /* d_in[23] c2_bias: cancels inside training-mode BN */
    const float* bn2_g   = (const float*)d_in[24];
    const float* bn2_b   = (const float*)d_in[25];
    const float* cls_w   = (const float*)d_in[26];
    const float* cls_b   = (const float*)d_in[27];
    const int* src = eidx;
    const int* dst = eidx + NE;
    float* out = (float*)d_out;

    float *p_xp, *p_xl1, *p_xr1, *p_agg1, *p_h, *p_xp2, *p_xl2, *p_xr2, *p_agg2, *p_h2;
    float *p_st1, *p_st2;
    cudaGetSymbolAddress((void**)&p_xp,   g_xp);
    cudaGetSymbolAddress((void**)&p_xl1,  g_xl1);
    cudaGetSymbolAddress((void**)&p_xr1,  g_xr1);
    cudaGetSymbolAddress((void**)&p_agg1, g_agg1);
    cudaGetSymbolAddress((void**)&p_h,    g_h);
    cudaGetSymbolAddress((void**)&p_xp2,  g_xp2);
    cudaGetSymbolAddress((void**)&p_xl2,  g_xl2);
    cudaGetSymbolAddress((void**)&p_xr2,  g_xr2);
    cudaGetSymbolAddress((void**)&p_agg2, g_agg2);
    cudaGetSymbolAddress((void**)&p_h2,   g_h2);
    cudaGetSymbolAddress((void**)&p_st1,  g_stats1);
    cudaGetSymbolAddress((void**)&p_st2,  g_stats2);

    // 1: histogram
    k_hist<<<1024, 256>>>(dst);
    // 2: scan (+ state reset for next execution)
    k_scan<<<1, 1024>>>();
    // 3: fused CSR scatter + layer-1 triple GEMM
    k_scatter_gemm1<<<SCAT_BLOCKS + GEMM1_BX * 3, 256>>>(src, dst, x,
        skip1_w, skip1_b, p_xp,
        c1_wl,   c1_bl,   p_xl1,
        c1_wr,   c1_br,   p_xr1);
    // 4: layer-1 attention (profiled launch)
    k_gat1<<<12500, 128>>>(eattr, c1_we, c1_att);

    // BN1 + skip + ELU
    k_bn_stats<HC1><<<512, HC1>>>(p_agg1, p_st1);
    k_bn_final<HC1><<<1, HC1>>>(p_st1);
    k_bn_elu<HC1><<<1024, 256>>>(p_agg1, p_st1, bn1_g, bn1_b, p_xp, p_h);

    // Layer 2 projections
    k_gemm3_l2<<<dim3((NN + 255) / 256, 3), 256>>>(p_h,
        skip2_w, skip2_b, p_xp2,
        c2_wl,   c2_bl,   p_xl2,
        c2_wr,   c2_br,   p_xr2);

    // Layer 2 attention
    k_gat2<<<12500, 128>>>(eattr, c2_we, c2_att);

    // BN2 + skip + ELU
    k_bn_stats<HIDD><<<512, HIDD>>>(p_agg2, p_st2);
    k_bn_final<HIDD><<<1, HIDD>>>(p_st2);
    k_bn_elu<HIDD><<<1024, 256>>>(p_agg2, p_st2, bn2_g, bn2_b, p_xp2, p_h2);

    // Pool + classify
    k_pool<<<NG, 256>>>(batch);
    k_classify<<<1, 128>>>(cls_w, cls_b, out);
}